// round 8
// baseline (speedup 1.0000x reference)
#include <cuda_runtime.h>
#include <cuda_bf16.h>
#include <math.h>

#define Fn 500
#define Hn 2000
#define FH 2500
#define Dn 64
#define Bn 4096
#define NB 592            // 4 CTAs/SM x 148 SMs, co-resident
#define EP 2560           // padded j extent for e matrix
#define IP 512            // padded i extent

// Scratch (zero-initialized at module load; pad regions never written)
__device__ __align__(16) float g_U[IP * 128];        // [i][ P1(=wu*a^2) | P2(=wu*a) ]
__device__ __align__(16) float g_V[EP * 128];        // [j][ b | b^2 ]
__device__ __align__(16) float g_B[EP];              // B_j = sum wu*(b - b^3/3)
__device__ __align__(16) float g_pre_f[Fn * Dn];     // a (exact path only)
__device__ __align__(16) float g_e[IP * EP];         // masked exp scores
__device__ __align__(16) float g_ssum_part[IP * 40]; // row-sum partials per j-tile
__device__ __align__(16) float g_ctx_part[20 * 500 * 64];
__device__ __align__(16) float g_ctx[Fn * Dn];
__device__ int g_maxa_bits = 0;    // idempotent across replays (same inputs)
__device__ int g_maxb_bits = 0;

// Replay-safe grid barrier
__device__ unsigned g_count = 0;
__device__ unsigned g_gen   = 0;
__device__ __forceinline__ void grid_bar() {
    __threadfence();
    __syncthreads();
    if (threadIdx.x == 0) {
        unsigned gen = atomicAdd(&g_gen, 0u);
        if (atomicAdd(&g_count, 1u) == NB - 1u) {
            g_count = 0u;
            __threadfence();
            atomicAdd(&g_gen, 1u);
        } else {
            while (atomicAdd(&g_gen, 0u) == gen) __nanosleep(32);
        }
    }
    __syncthreads();
}

typedef unsigned long long ull;
__device__ __forceinline__ ull pk2(float a, float b) {
    ull r; asm("mov.b64 %0, {%1,%2};" : "=l"(r) : "f"(a), "f"(b)); return r;
}
__device__ __forceinline__ void upk2(ull v, float& a, float& b) {
    asm("mov.b64 {%0,%1}, %2;" : "=f"(a), "=f"(b) : "l"(v));
}
__device__ __forceinline__ ull f2fma(ull a, ull b, ull c) {
    ull d; asm("fma.rn.f32x2 %0, %1, %2, %3;" : "=l"(d) : "l"(a), "l"(b), "l"(c)); return d;
}
__device__ __forceinline__ const float* full_row(const float* feat,
                                                 const float* hid, int j) {
    return (j < Fn) ? (feat + j * Dn) : (hid + (j - Fn) * Dn);
}

struct __align__(16) S1s {
    float sx[2][Dn];
    float red[4];
    float rmax[4];
};
struct __align__(16) S2a {          // S-GEMM tiles (transposed, padded rows)
    float Ut[32][68];
    float Vt[32][68];
};
struct __align__(16) S2b {          // e @ full
    float se[25][125];
    float spart[4][25][64];
};
struct __align__(16) S2x {          // exact fallback
    float pf[Dn];
    float wu[Dn];
    float wsum[4];
};
struct __align__(16) S3s {
    float val[8][50];
    float ctx[50][Dn];
};
union SMem { S1s s1; S2a s2a; S2b s2b; S2x s2x; S3s s3; };

__global__ __launch_bounds__(128, 4) void fused_all(
    const float* __restrict__ values,
    const float* __restrict__ feat,
    const float* __restrict__ hid,
    const float* __restrict__ Ww,
    const float* __restrict__ bw,
    const float* __restrict__ Wu,
    const float* __restrict__ mask,
    float* __restrict__ out)
{
    __shared__ SMem sm;
    __shared__ float s_swu;
    __shared__ int   s_exact;
    const int tid  = threadIdx.x;
    const int wid  = tid >> 5;
    const int lane = tid & 31;

    // ============ Stage 1: U, V, B, pre_f, global maxima ====================
    {
        const int r = tid >> 6;   // 0/1
        const int a = tid & 63;
        for (int t = blockIdx.x; t < 1500; t += NB) {
            __syncthreads();
            if (t < 1250) {
                const int row = t * 2 + r;                    // j: 0..2499
                float v = (row < Fn) ? feat[row * Dn + a]
                                     : hid[(row - Fn) * Dn + a];
                sm.s1.sx[r][a] = v;
                __syncthreads();
                float b = 0.f;
                #pragma unroll
                for (int k = 0; k < Dn; k++)
                    b += sm.s1.sx[r][k] * __ldg(&Ww[(Dn + k) * Dn + a]);
                const float wua = __ldg(&Wu[a]);
                const float b2 = b * b;
                g_V[row * 128 + a]      = b;
                g_V[row * 128 + 64 + a] = b2;
                float term = wua * (b - b * b2 * 0.33333334f);
                float mm = fabsf(b);
                #pragma unroll
                for (int off = 16; off > 0; off >>= 1) {
                    term += __shfl_xor_sync(0xffffffffu, term, off);
                    mm = fmaxf(mm, __shfl_xor_sync(0xffffffffu, mm, off));
                }
                if (lane == 0) { sm.s1.red[wid] = term; sm.s1.rmax[wid] = mm; }
                __syncthreads();
                if (tid == 0) {
                    g_B[row] = sm.s1.red[0] + sm.s1.red[1];
                    atomicMax(&g_maxb_bits,
                              __float_as_int(fmaxf(sm.s1.rmax[0], sm.s1.rmax[1])));
                } else if (tid == 64) {
                    g_B[row] = sm.s1.red[2] + sm.s1.red[3];
                    atomicMax(&g_maxb_bits,
                              __float_as_int(fmaxf(sm.s1.rmax[2], sm.s1.rmax[3])));
                }
            } else {
                const int row = (t - 1250) * 2 + r;           // i: 0..499
                sm.s1.sx[r][a] = feat[row * Dn + a];
                __syncthreads();
                float av = __ldg(&bw[a]);
                #pragma unroll
                for (int k = 0; k < Dn; k++)
                    av += sm.s1.sx[r][k] * __ldg(&Ww[k * Dn + a]);
                const float wua = __ldg(&Wu[a]);
                g_pre_f[row * Dn + a]   = av;
                g_U[row * 128 + a]      = wua * av * av;
                g_U[row * 128 + 64 + a] = wua * av;
                float mm = fabsf(av);
                #pragma unroll
                for (int off = 16; off > 0; off >>= 1)
                    mm = fmaxf(mm, __shfl_xor_sync(0xffffffffu, mm, off));
                if (lane == 0) sm.s1.rmax[wid] = mm;
                __syncthreads();
                if (tid == 0)
                    atomicMax(&g_maxa_bits,
                              __float_as_int(fmaxf(sm.s1.rmax[0], sm.s1.rmax[1])));
                if (tid == 64)
                    atomicMax(&g_maxa_bits,
                              __float_as_int(fmaxf(sm.s1.rmax[2], sm.s1.rmax[3])));
            }
        }
    }

    grid_bar();

    // ---- error bound -> path selection (uniform across blocks)
    if (wid == 0) {
        float s = fabsf(__ldg(&Wu[lane])) + fabsf(__ldg(&Wu[lane + 32]));
        #pragma unroll
        for (int off = 16; off > 0; off >>= 1)
            s += __shfl_xor_sync(0xffffffffu, s, off);
        if (lane == 0) s_swu = s;
    }
    __syncthreads();
    if (tid == 0) {
        float bnd = __int_as_float(g_maxa_bits) + __int_as_float(g_maxb_bits);
        float b5 = bnd * bnd; b5 = b5 * b5 * bnd;
        s_exact = (0.1333334f * b5 * s_swu >= 1e-4f) ? 1 : 0;
    }
    __syncthreads();
    const int exact = s_exact;

    // ============ Stage 2a: e = mask * exp(B_j - U V^T) =====================
    if (!exact) {
        if (blockIdx.x < 320) {
            const int it = blockIdx.x / 40;       // 0..7
            const int jt = blockIdx.x % 40;       // 0..39
            const int i0 = it * 64;
            const int j0 = jt * 64;
            const int tx = tid & 7;               // j-octet
            const int ty = tid >> 3;              // i-quad
            ull acc[16];
            #pragma unroll
            for (int q = 0; q < 16; q++) acc[q] = 0ull;

            const int li = tid >> 1;              // load row 0..63
            const int kq = tid & 1;

            for (int kc = 0; kc < 128; kc += 32) {
                __syncthreads();
                #pragma unroll
                for (int q = 0; q < 4; q++) {
                    const int kk = kq * 16 + q * 4;
                    float4 u4 = *(const float4*)&g_U[(i0 + li) * 128 + kc + kk];
                    sm.s2a.Ut[kk + 0][li] = u4.x;
                    sm.s2a.Ut[kk + 1][li] = u4.y;
                    sm.s2a.Ut[kk + 2][li] = u4.z;
                    sm.s2a.Ut[kk + 3][li] = u4.w;
                    float4 v4 = *(const float4*)&g_V[(j0 + li) * 128 + kc + kk];
                    sm.s2a.Vt[kk + 0][li] = v4.x;
                    sm.s2a.Vt[kk + 1][li] = v4.y;
                    sm.s2a.Vt[kk + 2][li] = v4.z;
                    sm.s2a.Vt[kk + 3][li] = v4.w;
                }
                __syncthreads();
                #pragma unroll
                for (int kk = 0; kk < 32; kk++) {
                    float4 u = *(const float4*)&sm.s2a.Ut[kk][ty * 4];
                    const ull* vp = (const ull*)&sm.s2a.Vt[kk][tx * 8];
                    ull v0 = vp[0], v1 = vp[1], v2 = vp[2], v3 = vp[3];
                    ull u0 = pk2(u.x, u.x), u1 = pk2(u.y, u.y);
                    ull u2 = pk2(u.z, u.z), u3 = pk2(u.w, u.w);
                    acc[0]  = f2fma(u0, v0, acc[0]);
                    acc[1]  = f2fma(u0, v1, acc[1]);
                    acc[2]  = f2fma(u0, v2, acc[2]);
                    acc[3]  = f2fma(u0, v3, acc[3]);
                    acc[4]  = f2fma(u1, v0, acc[4]);
                    acc[5]  = f2fma(u1, v1, acc[5]);
                    acc[6]  = f2fma(u1, v2, acc[6]);
                    acc[7]  = f2fma(u1, v3, acc[7]);
                    acc[8]  = f2fma(u2, v0, acc[8]);
                    acc[9]  = f2fma(u2, v1, acc[9]);
                    acc[10] = f2fma(u2, v2, acc[10]);
                    acc[11] = f2fma(u2, v3, acc[11]);
                    acc[12] = f2fma(u3, v0, acc[12]);
                    acc[13] = f2fma(u3, v1, acc[13]);
                    acc[14] = f2fma(u3, v2, acc[14]);
                    acc[15] = f2fma(u3, v3, acc[15]);
                }
            }

            // epilogue: e + row-sum partials
            #pragma unroll
            for (int ii = 0; ii < 4; ii++) {
                const int i = i0 + ty * 4 + ii;
                float rsum = 0.f;
                #pragma unroll
                for (int jj = 0; jj < 4; jj++) {
                    const int j = j0 + tx * 8 + jj * 2;
                    float d0, d1; upk2(acc[ii * 4 + jj], d0, d1);
                    float s0 = __ldg(&g_B[j])     - d0;
                    float s1 = __ldg(&g_B[j + 1]) - d1;
                    float e0 = 0.f, e1 = 0.f;
                    if (i < Fn) {
                        if (j < FH) {
                            float m0 = __ldg(&mask[(size_t)i * FH + j]);
                            if (m0 != 0.f) e0 = __expf(s0);
                        }
                        if (j + 1 < FH) {
                            float m1 = __ldg(&mask[(size_t)i * FH + j + 1]);
                            if (m1 != 0.f) e1 = __expf(s1);
                        }
                    }
                    *(float2*)&g_e[(size_t)i * EP + j] = make_float2(e0, e1);
                    rsum += e0 + e1;
                }
                rsum += __shfl_xor_sync(0xffffffffu, rsum, 1);
                rsum += __shfl_xor_sync(0xffffffffu, rsum, 2);
                rsum += __shfl_xor_sync(0xffffffffu, rsum, 4);
                if (tx == 0) g_ssum_part[i * 40 + jt] = rsum;
            }
        }
    } else {
        // exact fallback: brute-force tanh per masked pair
        for (int i = blockIdx.x; i < Fn; i += NB) {
            if (tid < Dn) {
                sm.s2x.pf[tid] = g_pre_f[i * Dn + tid];
                sm.s2x.wu[tid] = __ldg(&Wu[tid]);
            }
            __syncthreads();
            float wsum = 0.f;
            for (int j = tid; j < FH; j += 128) {
                float m = __ldg(&mask[(size_t)i * FH + j]);
                float e = 0.f;
                if (m != 0.f) {
                    float s = 0.f;
                    for (int k = 0; k < Dn; k++)
                        s += tanhf(sm.s2x.pf[k] + g_V[j * 128 + k]) * sm.s2x.wu[k];
                    e = expf(s);
                }
                g_e[(size_t)i * EP + j] = e;
                wsum += e;
            }
            #pragma unroll
            for (int off = 16; off > 0; off >>= 1)
                wsum += __shfl_xor_sync(0xffffffffu, wsum, off);
            if (lane == 0) sm.s2x.wsum[wid] = wsum;
            __syncthreads();
            if (tid == 0)
                g_ssum_part[i * 40] = (sm.s2x.wsum[0] + sm.s2x.wsum[1]) +
                                      (sm.s2x.wsum[2] + sm.s2x.wsum[3]);
            else if (tid >= 1 && tid < 40)
                g_ssum_part[i * 40 + tid] = 0.f;
            __syncthreads();
        }
    }

    grid_bar();

    // ============ Stage 2b: ctx partials = e @ full (split-K, 20 chunks) ====
    if (blockIdx.x < 400) {
        const int it2 = blockIdx.x / 20;      // 0..19 -> 25 i's
        const int jc  = blockIdx.x % 20;      // 0..19 -> 125 j's
        const int i0  = it2 * 25;
        const int jb  = jc * 125;

        for (int idx = tid; idx < 25 * 125; idx += 128) {
            int r = idx / 125, c = idx - r * 125;
            sm.s2b.se[r][c] = g_e[(size_t)(i0 + r) * EP + jb + c];
        }
        __syncthreads();

        const int kp = tid & 31;              // k-pair
        const int jp = tid >> 5;              // 0..3
        ull acc[25];
        #pragma unroll
        for (int q = 0; q < 25; q++) acc[q] = 0ull;

        for (int jj = jp; jj < 125; jj += 4) {
            const int j = jb + jj;
            const float* fr = full_row(feat, hid, j);
            float2 fv = *(const float2*)(fr + kp * 2);
            ull fvp = pk2(fv.x, fv.y);
            #pragma unroll
            for (int q = 0; q < 25; q++) {
                float e = sm.s2b.se[q][jj];
                acc[q] = f2fma(pk2(e, e), fvp, acc[q]);
            }
        }
        __syncthreads();
        #pragma unroll
        for (int q = 0; q < 25; q++) {
            float a, b; upk2(acc[q], a, b);
            sm.s2b.spart[jp][q][kp * 2]     = a;
            sm.s2b.spart[jp][q][kp * 2 + 1] = b;
        }
        __syncthreads();
        for (int idx = tid; idx < 25 * 64; idx += 128) {
            int q = idx >> 6, k = idx & 63;
            float v = (sm.s2b.spart[0][q][k] + sm.s2b.spart[1][q][k]) +
                      (sm.s2b.spart[2][q][k] + sm.s2b.spart[3][q][k]);
            g_ctx_part[((size_t)jc * 500 + i0 + q) * 64 + k] = v;
        }
    }

    grid_bar();

    // ============ Stage 2c: reduce partials, divide by ssum ================
    if (blockIdx.x < 250) {
        const int i = blockIdx.x * 2 + (tid >> 6);
        const int k = tid & 63;
        const float4* sp = (const float4*)&g_ssum_part[i * 40];
        float ss = 0.f;
        #pragma unroll
        for (int q = 0; q < 10; q++) {
            float4 s4 = __ldg(sp + q);
            ss += ((s4.x + s4.y) + (s4.z + s4.w));
        }
        const float inv = (ss > 0.f) ? (1.0f / ss) : 1.0f;
        float c0 = 0.f, c1 = 0.f, c2 = 0.f, c3 = 0.f;
        #pragma unroll
        for (int jc = 0; jc < 20; jc += 4) {
            c0 += __ldg(&g_ctx_part[((size_t)(jc + 0) * 500 + i) * 64 + k]);
            c1 += __ldg(&g_ctx_part[((size_t)(jc + 1) * 500 + i) * 64 + k]);
            c2 += __ldg(&g_ctx_part[((size_t)(jc + 2) * 500 + i) * 64 + k]);
            c3 += __ldg(&g_ctx_part[((size_t)(jc + 3) * 500 + i) * 64 + k]);
        }
        g_ctx[i * Dn + k] = ((c0 + c1) + (c2 + c3)) * inv;
    }

    grid_bar();

    // ============ Stage 3: out = values @ ctx ==============================
    if (blockIdx.x < 512) {
        const int rb   = blockIdx.x;
        const int tx   = tid & 15;
        const int ty   = tid >> 4;
        const int col0 = tx * 4;
        const int row  = rb * 8 + ty;
        ull a0 = 0ull, a1 = 0ull;

        for (int f0 = 0; f0 < Fn; f0 += 50) {
            for (int idx = tid; idx < 8 * 50; idx += 128) {
                int r = idx / 50, f = idx - r * 50;
                sm.s3.val[r][f] = values[(size_t)(rb * 8 + r) * Fn + f0 + f];
            }
            for (int idx = tid; idx < 50 * Dn; idx += 128) {
                int f = idx >> 6, c = idx & 63;
                sm.s3.ctx[f][c] = g_ctx[(f0 + f) * Dn + c];
            }
            __syncthreads();
            #pragma unroll
            for (int f = 0; f < 50; f++) {
                float v = sm.s3.val[ty][f];
                ull vp = pk2(v, v);
                const ull* cp = (const ull*)&sm.s3.ctx[f][col0];
                a0 = f2fma(vp, cp[0], a0);
                a1 = f2fma(vp, cp[1], a1);
            }
            __syncthreads();
        }
        float a, b, c, d;
        upk2(a0, a, b); upk2(a1, c, d);
        *(float4*)&out[(size_t)row * Dn + col0] = make_float4(a, b, c, d);
    }
}

extern "C" void kernel_launch(void* const* d_in, const int* in_sizes, int n_in,
                              void* d_out, int out_size)
{
    const float* values   = (const float*)d_in[0];
    const float* feat_emb = (const float*)d_in[1];
    const float* hid_emb  = (const float*)d_in[2];
    const float* Ww       = (const float*)d_in[3];
    const float* bw       = (const float*)d_in[4];
    const float* Wu       = (const float*)d_in[5];
    const float* mask     = (const float*)d_in[6];
    float* out            = (float*)d_out;

    fused_all<<<NB, 128>>>(values, feat_emb, hid_emb, Ww, bw, Wu, mask, out);
}